// round 1
// baseline (speedup 1.0000x reference)
#include <cuda_runtime.h>
#include <cstdint>

#define BATCH 64
#define TLEN 160
#define HID 256
#define MAXLEN 2000

// scratch: inclusive cumsum of durations per batch
__device__ int g_csum[BATCH * TLEN];

// Kernel 1: per-batch inclusive cumsum via warp scan (5 chunks of 32),
// also writes mel_len (= total) as float into the output tail.
__global__ void lr_cumsum_kernel(const int* __restrict__ dur, float* __restrict__ mel_out) {
    int b = blockIdx.x;
    int lane = threadIdx.x;  // 32 threads
    int carry = 0;
#pragma unroll
    for (int c = 0; c < TLEN / 32; ++c) {
        int i = c * 32 + lane;
        int v = dur[b * TLEN + i];
#pragma unroll
        for (int off = 1; off < 32; off <<= 1) {
            int n = __shfl_up_sync(0xffffffffu, v, off);
            if (lane >= off) v += n;
        }
        int total = __shfl_sync(0xffffffffu, v, 31);
        v += carry;
        carry += total;
        g_csum[b * TLEN + i] = v;
    }
    if (lane == 31) mel_out[b] = (float)carry;
}

// Kernel 2: one warp per output frame. 256 threads = 8 frames per block.
// Each lane moves 2 float4 (32 bytes) of each of the two 1KB output rows.
__global__ __launch_bounds__(256) void lr_regulate_kernel(
    const float* __restrict__ x,
    const float* __restrict__ penc,
    float* __restrict__ out,
    float* __restrict__ pos)
{
    __shared__ int s_csum[TLEN];
    const int b = blockIdx.y;
    const int tid = threadIdx.x;
    if (tid < TLEN) s_csum[tid] = g_csum[b * TLEN + tid];
    __syncthreads();

    const int warp = tid >> 5;
    const int lane = tid & 31;
    const int f = blockIdx.x * 8 + warp;

    const int mel = s_csum[TLEN - 1];
    const bool valid = (f < mel);

    float4 o0, o1, p0, p1;
    if (valid) {
        // searchsorted(csum, f, side='right'): first index with csum[idx] > f
        int lo = 0, hi = TLEN;
#pragma unroll 8
        while (lo < hi) {
            int mid = (lo + hi) >> 1;
            if (s_csum[mid] <= f) lo = mid + 1; else hi = mid;
        }
        int idx = lo < (TLEN - 1) ? lo : (TLEN - 1);
        int excl = idx ? s_csum[idx - 1] : 0;
        int pw = f - excl;

        const float4* xr = (const float4*)(x + ((size_t)b * TLEN + idx) * HID);
        const float4* pr = (const float4*)(penc + (size_t)pw * HID);
        o0 = xr[lane];      o1 = xr[lane + 32];
        p0 = pr[lane];      p1 = pr[lane + 32];
    } else {
        o0 = o1 = p0 = p1 = make_float4(0.f, 0.f, 0.f, 0.f);
    }

    const size_t row = ((size_t)b * MAXLEN + f) * HID;
    float4* ow = (float4*)(out + row);
    float4* pw4 = (float4*)(pos + row);
    ow[lane] = o0;        ow[lane + 32] = o1;
    pw4[lane] = p0;       pw4[lane + 32] = p1;
}

extern "C" void kernel_launch(void* const* d_in, const int* in_sizes, int n_in,
                              void* d_out, int out_size) {
    const float* x    = (const float*)d_in[0];       // (64,160,256) f32
    const float* penc = (const float*)d_in[1];       // (2001,256) f32
    const int*   dur  = (const int*)d_in[2];         // (64,160) int32
    // d_in[3] (max_len scalar) unused — fixed at 2000

    float* out = (float*)d_out;                                   // (64,2000,256)
    float* pos = out + (size_t)BATCH * MAXLEN * HID;              // (64,2000,256)
    float* mel = out + 2 * (size_t)BATCH * MAXLEN * HID;          // (64,)

    lr_cumsum_kernel<<<BATCH, 32>>>(dur, mel);
    dim3 grid(MAXLEN / 8, BATCH);
    lr_regulate_kernel<<<grid, 256>>>(x, penc, out, pos);
}

// round 2
// speedup vs baseline: 1.1972x; 1.1972x over previous
#include <cuda_runtime.h>
#include <cstdint>

#define BATCH 64
#define TLEN 160
#define HID 256
#define MAXLEN 2000

// Single fused kernel: one block = 8 output frames of one batch.
// Each block re-derives the per-batch inclusive cumsum of durations
// (640 B of int32, L2-resident across the 250 blocks of a batch) via
// 5 warp scans + chunk-offset combine, then each warp binary-searches
// its frame and streams 2 x 1KB rows (x-gather and penc-gather) out.
__global__ __launch_bounds__(256) void lr_fused_kernel(
    const float* __restrict__ x,
    const float* __restrict__ penc,
    const int*   __restrict__ dur,
    float* __restrict__ out,
    float* __restrict__ pos,
    float* __restrict__ mel_out)
{
    __shared__ int s_csum[TLEN];
    __shared__ int s_tot[TLEN / 32];   // 5 chunk totals

    const int b    = blockIdx.y;
    const int tid  = threadIdx.x;
    const int lane = tid & 31;
    const int warp = tid >> 5;

    // ---- in-block inclusive scan of duration[b, :] ----
    int v = 0;
    if (tid < TLEN) {
        v = dur[b * TLEN + tid];
#pragma unroll
        for (int off = 1; off < 32; off <<= 1) {
            int n = __shfl_up_sync(0xffffffffu, v, off);
            if (lane >= off) v += n;
        }
        if (lane == 31) s_tot[warp] = v;
    }
    __syncthreads();
    if (tid < TLEN) {
        int add = 0;
#pragma unroll
        for (int i = 0; i < TLEN / 32; ++i)
            if (i < warp) add += s_tot[i];
        s_csum[tid] = v + add;
    }
    __syncthreads();

    const int mel = s_csum[TLEN - 1];
    if (blockIdx.x == 0 && tid == 0) mel_out[b] = (float)mel;

    // ---- one warp per output frame ----
    const int f = blockIdx.x * 8 + warp;
    const bool valid = (f < mel);

    float4 o0, o1, p0, p1;
    if (valid) {
        // searchsorted(csum, f, side='right'): first idx with csum[idx] > f
        int lo = 0, hi = TLEN;
#pragma unroll 8
        while (lo < hi) {
            int mid = (lo + hi) >> 1;
            if (s_csum[mid] <= f) lo = mid + 1; else hi = mid;
        }
        int idx  = lo < (TLEN - 1) ? lo : (TLEN - 1);
        int excl = idx ? s_csum[idx - 1] : 0;
        int pw   = f - excl;

        const float4* xr = (const float4*)(x + ((size_t)b * TLEN + idx) * HID);
        const float4* pr = (const float4*)(penc + (size_t)pw * HID);
        o0 = xr[lane];  o1 = xr[lane + 32];
        p0 = pr[lane];  p1 = pr[lane + 32];
    } else {
        o0 = o1 = p0 = p1 = make_float4(0.f, 0.f, 0.f, 0.f);
    }

    const size_t row = ((size_t)b * MAXLEN + f) * HID;
    float4* ow = (float4*)(out + row);
    float4* pw4 = (float4*)(pos + row);
    // streaming stores: written once, never re-read here — keep L2 for x rows
    __stcs(ow + lane, o0);
    __stcs(ow + lane + 32, o1);
    __stcs(pw4 + lane, p0);
    __stcs(pw4 + lane + 32, p1);
}

extern "C" void kernel_launch(void* const* d_in, const int* in_sizes, int n_in,
                              void* d_out, int out_size) {
    const float* x    = (const float*)d_in[0];   // (64,160,256) f32
    const float* penc = (const float*)d_in[1];   // (2001,256) f32
    const int*   dur  = (const int*)d_in[2];     // (64,160) int32
    // d_in[3] (max_len scalar) unused — fixed at 2000

    float* out = (float*)d_out;                                   // (64,2000,256)
    float* pos = out + (size_t)BATCH * MAXLEN * HID;              // (64,2000,256)
    float* mel = out + 2 * (size_t)BATCH * MAXLEN * HID;          // (64,)

    dim3 grid(MAXLEN / 8, BATCH);
    lr_fused_kernel<<<grid, 256>>>(x, penc, dur, out, pos, mel);
}